// round 15
// baseline (speedup 1.0000x reference)
#include <cuda_runtime.h>
#include <cstdint>

#define NB   4
#define TQ   2048
#define NE   1024
#define HD   128
#define TKF  4096
#define NM   16384

typedef unsigned long long ull;

// ---------------- packed f32x2 helpers (sm_103a only) ----------------
__device__ __forceinline__ ull dup2(float x) {
    ull r; asm("mov.b64 %0, {%1, %1};" : "=l"(r) : "f"(x)); return r;
}
__device__ __forceinline__ float2 u2f(ull v) {
    float2 r; asm("mov.b64 {%0, %1}, %2;" : "=f"(r.x), "=f"(r.y) : "l"(v)); return r;
}
__device__ __forceinline__ ull ffma2(ull a, ull b, ull c) {
    ull d; asm("fma.rn.f32x2 %0, %1, %2, %3;" : "=l"(d) : "l"(a), "l"(b), "l"(c)); return d;
}
__device__ __forceinline__ ull fmul2(ull a, ull b) {
    ull d; asm("mul.rn.f32x2 %0, %1, %2;" : "=l"(d) : "l"(a), "l"(b)); return d;
}

// ---------------- cp.async helpers ----------------
__device__ __forceinline__ void cp16(uint32_t dst_smem, const void* src) {
    asm volatile("cp.async.ca.shared.global [%0], [%1], 16;"
                 :: "r"(dst_smem), "l"(src));
}
__device__ __forceinline__ void cp_commit() {
    asm volatile("cp.async.commit_group;");
}
__device__ __forceinline__ void cp_wait0() {
    asm volatile("cp.async.wait_group 0;");
}
__device__ __forceinline__ void cp_wait1() {
    asm volatile("cp.async.wait_group 1;");
}

// ---------------- device scratch ----------------
__device__ float g_q [(size_t)NB * TQ  * HD];
__device__ float g_kf[(size_t)NB * TKF * HD];
__device__ float g_vf[(size_t)NB * TKF * HD];
// key-pair-interleaved copy of mem_keys
__device__ float g_ki[(size_t)NB * NM * HD];
// attention split-K partials: [half][b][q]
__device__ float g_am[(size_t)2 * NB * TQ];
__device__ float g_al[(size_t)2 * NB * TQ];
__device__ float g_ao[(size_t)2 * NB * TQ * HD];

// =========================================================================
// 0) key interleave pre-pass: pack key pairs along dims
// =========================================================================
__global__ __launch_bounds__(256) void interleave_kernel(
    const float* __restrict__ mem_keys)
{
    const int f4 = blockIdx.x * 256 + threadIdx.x;
    const int d2 = f4 & 63;
    const int p  = (f4 >> 6) & 8191;
    const int b  = f4 >> 19;
    const float2* r0 = (const float2*)(mem_keys + ((size_t)b * NM + 2 * p)     * HD) + d2;
    const float2* r1 = (const float2*)(mem_keys + ((size_t)b * NM + 2 * p + 1) * HD) + d2;
    float2 a = *r0, c = *r1;
    ((float4*)g_ki)[f4] = make_float4(a.x, c.x, a.y, c.y);
}

// =========================================================================
// 1) prefix copy
// =========================================================================
__global__ __launch_bounds__(256) void copy_prefix_kernel(
    const float* __restrict__ ki, const float* __restrict__ vi,
    const int* __restrict__ idxp)
{
    const int s  = idxp[0] * HD;
    const int e4 = blockIdx.x * 256 + threadIdx.x;
    const int d4 = e4 & 31;
    const int t  = (e4 >> 5) & (TQ - 1);
    const int b  = e4 >> 16;
    const size_t src = ((size_t)b * TQ + t) * NE + s + (size_t)d4 * 4;
    const size_t dst = ((size_t)b * TKF + t) * HD + (size_t)d4 * 4;
    *(float4*)(g_kf + dst) = *(const float4*)(ki + src);
    *(float4*)(g_vf + dst) = *(const float4*)(vi + src);
}

// =========================================================================
// 2) fused projection GEMM (packed FFMA2) — unchanged
// =========================================================================
__global__ __launch_bounds__(256) void proj_kernel(
    const float* __restrict__ X,
    const float* __restrict__ Wq, const float* __restrict__ Wk,
    const float* __restrict__ Wv,
    const float* __restrict__ bq, const float* __restrict__ bk,
    const float* __restrict__ bv)
{
    __shared__ float As[64][17];
    __shared__ float Bs[16][128];
    const int mode = blockIdx.y;
    const float* W    = (mode == 0) ? Wq : (mode == 1) ? Wk : Wv;
    const float* bias = (mode == 0) ? bq : (mode == 1) ? bk : bv;
    float* dst        = (mode == 0) ? g_q : (mode == 1) ? g_kf : g_vf;

    const int t   = threadIdx.x;
    const int bm0 = blockIdx.x * 64;
    const int tr  = t >> 4;
    const int tc  = t & 15;

    ull acc[4][4];
    #pragma unroll
    for (int i = 0; i < 4; i++)
        #pragma unroll
        for (int j = 0; j < 4; j++) acc[i][j] = 0ULL;

    const int ar = t >> 2, ac = (t & 3) * 4;
    const int br = t >> 5, bc = (t & 31) * 4;

    for (int k0 = 0; k0 < NE; k0 += 16) {
        float4 av = *(const float4*)(X + (size_t)(bm0 + ar) * NE + k0 + ac);
        As[ar][ac + 0] = av.x; As[ar][ac + 1] = av.y;
        As[ar][ac + 2] = av.z; As[ar][ac + 3] = av.w;
        *(float4*)(&Bs[br][bc])     = *(const float4*)(W + (size_t)(k0 + br) * HD + bc);
        *(float4*)(&Bs[br + 8][bc]) = *(const float4*)(W + (size_t)(k0 + br + 8) * HD + bc);
        __syncthreads();
        #pragma unroll
        for (int kk = 0; kk < 16; kk++) {
            ull pa[4];
            #pragma unroll
            for (int i = 0; i < 4; i++) pa[i] = dup2(As[tr * 4 + i][kk]);
            ulonglong2 b01 = *(const ulonglong2*)(&Bs[kk][tc * 8]);
            ulonglong2 b23 = *(const ulonglong2*)(&Bs[kk][tc * 8 + 4]);
            #pragma unroll
            for (int i = 0; i < 4; i++) {
                acc[i][0] = ffma2(pa[i], b01.x, acc[i][0]);
                acc[i][1] = ffma2(pa[i], b01.y, acc[i][1]);
                acc[i][2] = ffma2(pa[i], b23.x, acc[i][2]);
                acc[i][3] = ffma2(pa[i], b23.y, acc[i][3]);
            }
        }
        __syncthreads();
    }

    float4 bb0 = *(const float4*)(bias + tc * 8);
    float4 bb1 = *(const float4*)(bias + tc * 8 + 4);
    #pragma unroll
    for (int i = 0; i < 4; i++) {
        int row = bm0 + tr * 4 + i;
        int bi  = row >> 11;
        int tt  = row & (TQ - 1);
        size_t orow = (mode == 0) ? (size_t)row : ((size_t)bi * TKF + TQ + tt);
        float2 a0 = u2f(acc[i][0]), a1 = u2f(acc[i][1]);
        float2 a2 = u2f(acc[i][2]), a3 = u2f(acc[i][3]);
        float4 o0 = make_float4(a0.x + bb0.x, a0.y + bb0.y, a1.x + bb0.z, a1.y + bb0.w);
        float4 o1 = make_float4(a2.x + bb1.x, a2.y + bb1.y, a3.x + bb1.z, a3.y + bb1.w);
        *(float4*)(dst + orow * HD + tc * 8)     = o0;
        *(float4*)(dst + orow * HD + tc * 8 + 4) = o1;
    }
}

// =========================================================================
// 3) causal flash attention — split-K (z=2), phase-split software pipeline:
//    K(t+1) loads during softmax+PV(t); V(t+1) loads during QK(t+1).
//    All arithmetic identical to R14 passing kernel.
// =========================================================================
#define ATTN_SMEM (3 * 32768 + 64 * 36 * 4)

__global__ __launch_bounds__(256, 2) void attn_kernel()
{
    extern __shared__ float smem_dyn[];
    float4* Qs = (float4*)smem_dyn;
    float4* Ks = Qs + 64 * 32;
    float4* Vs = Ks + 64 * 32;
    float*  Ss = (float*)(Vs + 64 * 32);

    const int t  = threadIdx.x;
    const int b  = blockIdx.y;
    const int qb = blockIdx.x;
    const int z  = blockIdx.z;
    const int tq = t >> 4;
    const int tk = t & 15;
    const float scale = 0.08838834764831845f;

    const float4* qsrc = (const float4*)(g_q + ((size_t)(b * TQ + qb * 64)) * HD);
    #pragma unroll
    for (int i = 0; i < 8; i++) {
        int idx = t + i * 256; int r = idx >> 5, c = idx & 31;
        Qs[r * 32 + (c ^ ((r >> 2) & 7))] = qsrc[idx];
    }

    float m[4], l[4];
    ull ac2[4][4];
    #pragma unroll
    for (int i = 0; i < 4; i++) {
        m[i] = -1e30f; l[i] = 0.f;
        #pragma unroll
        for (int j = 0; j < 4; j++) ac2[i][j] = 0ULL;
    }

    const float4* kbase = (const float4*)(g_kf + ((size_t)b * TKF) * HD);
    const float4* vbase = (const float4*)(g_vf + ((size_t)b * TKF) * HD);
    const int nt   = qb + 33;
    const int mid  = (nt + 1) >> 1;
    const int t0   = z ? mid : 0;
    const int tend = z ? nt : mid;

    const uint32_t kd = (uint32_t)__cvta_generic_to_shared(Ks);
    const uint32_t vd = (uint32_t)__cvta_generic_to_shared(Vs);

    // prologue: K(t0) then V(t0), separate commit groups
    {
        const float4* ks = kbase + (size_t)t0 * 2048;
        #pragma unroll
        for (int i = 0; i < 8; i++) {
            int idx = t + i * 256; int r = idx >> 5, c = idx & 31;
            uint32_t off = (uint32_t)(r * 32 + (c ^ ((r >> 2) & 7))) * 16u;
            cp16(kd + off, ks + idx);
        }
        cp_commit();
        const float4* vs = vbase + (size_t)t0 * 2048;
        #pragma unroll
        for (int i = 0; i < 8; i++) {
            int idx = t + i * 256; int r = idx >> 5, c = idx & 31;
            uint32_t off = (uint32_t)(r * 32 + (c ^ ((r >> 2) & 7))) * 16u;
            cp16(vd + off, vs + idx);
        }
        cp_commit();
    }

    for (int tile = t0; tile < tend; tile++) {
        const bool more = (tile + 1 < tend);

        // ---- wait K(tile) (newest group V(tile) may stay in flight) ----
        cp_wait1();
        __syncthreads();

        // ---- QK^T (packed, identical) ----
        ull s2[4][4];
        #pragma unroll
        for (int i = 0; i < 4; i++)
            #pragma unroll
            for (int j = 0; j < 4; j++) s2[i][j] = 0ULL;

        #pragma unroll 4
        for (int c = 0; c < 32; c++) {
            ulonglong2 a2[4], k2[4];
            #pragma unroll
            for (int i = 0; i < 4; i++)
                a2[i] = *(const ulonglong2*)&Qs[(4 * tq + i) * 32 + (c ^ (tq & 7))];
            #pragma unroll
            for (int j = 0; j < 4; j++)
                k2[j] = *(const ulonglong2*)&Ks[(4 * tk + j) * 32 + (c ^ (tk & 7))];
            #pragma unroll
            for (int i = 0; i < 4; i++)
                #pragma unroll
                for (int j = 0; j < 4; j++)
                    s2[i][j] = ffma2(a2[i].x, k2[j].x,
                               ffma2(a2[i].y, k2[j].y, s2[i][j]));
        }
        __syncthreads();               // all threads done reading Ks

        // ---- issue K(tile+1) into Ks (overlaps softmax + PV) ----
        if (more) {
            const float4* ks = kbase + (size_t)(tile + 1) * 2048;
            #pragma unroll
            for (int i = 0; i < 8; i++) {
                int idx = t + i * 256; int r = idx >> 5, c = idx & 31;
                uint32_t off = (uint32_t)(r * 32 + (c ^ ((r >> 2) & 7))) * 16u;
                cp16(kd + off, ks + idx);
            }
            cp_commit();
        }

        float s[4][4];
        const bool lastTile = (tile == nt - 1);
        #pragma unroll
        for (int i = 0; i < 4; i++)
            #pragma unroll
            for (int j = 0; j < 4; j++) {
                float2 p = u2f(s2[i][j]);
                s[i][j] = (p.x + p.y) * scale;
                if (lastTile && (4 * tk + j > 4 * tq + i)) s[i][j] = -1e30f;
            }

        // ---- online softmax (identical) ----
        float tmax[4];
        #pragma unroll
        for (int i = 0; i < 4; i++)
            tmax[i] = fmaxf(fmaxf(s[i][0], s[i][1]), fmaxf(s[i][2], s[i][3]));
        #pragma unroll
        for (int o = 1; o < 16; o <<= 1)
            #pragma unroll
            for (int i = 0; i < 4; i++)
                tmax[i] = fmaxf(tmax[i], __shfl_xor_sync(0xffffffffu, tmax[i], o));

        float corr[4], rs[4];
        #pragma unroll
        for (int i = 0; i < 4; i++) {
            float mn = fmaxf(m[i], tmax[i]);
            corr[i] = __expf(m[i] - mn);
            m[i] = mn;
            rs[i] = 0.f;
            #pragma unroll
            for (int j = 0; j < 4; j++) {
                s[i][j] = __expf(s[i][j] - mn);
                rs[i] += s[i][j];
            }
        }
        #pragma unroll
        for (int o = 1; o < 16; o <<= 1)
            #pragma unroll
            for (int i = 0; i < 4; i++)
                rs[i] += __shfl_xor_sync(0xffffffffu, rs[i], o);
        #pragma unroll
        for (int i = 0; i < 4; i++) {
            l[i] = l[i] * corr[i] + rs[i];
            ull c2 = dup2(corr[i]);
            #pragma unroll
            for (int j = 0; j < 4; j++) ac2[i][j] = fmul2(ac2[i][j], c2);
        }

        // ---- wait V(tile): if K(tile+1) pending, wait1; else wait0 ----
        if (more) cp_wait1(); else cp_wait0();

        // ---- P @ V in two 32-key stages (identical) ----
        #pragma unroll
        for (int stage = 0; stage < 2; stage++) {
            __syncthreads();
            if ((tk >> 3) == stage) {
                #pragma unroll
                for (int i = 0; i < 4; i++)
                    *(float4*)&Ss[(4 * tq + i) * 36 + 4 * (tk & 7)] =
                        make_float4(s[i][0], s[i][1], s[i][2], s[i][3]);
            }
            __syncthreads();

            #pragma unroll 2
            for (int jj = 0; jj < 8; jj++) {
                float4 p[4];
                #pragma unroll
                for (int i = 0; i < 4; i++)
                    p[i] = *(const float4*)&Ss[(4 * tq + i) * 36 + jj * 4];
                #pragma unroll
                for (int e = 0; e < 4; e++) {
                    int j = stage * 32 + jj * 4 + e;
                    int key = (j >> 2) & 7;
                    ulonglong2 v0 = *(const ulonglong2*)&Vs[j * 32 + (tk ^ key)];
                    ulonglong2 v1 = *(const ulonglong2*)&Vs[j * 32 + ((16 + tk) ^ key)];
                    #pragma unroll
                    for (int i = 0; i < 4; i++) {
                        float pv = (e == 0) ? p[i].x : (e == 1) ? p[i].y
                                 : (e == 2) ? p[i].z : p[i].w;
                        ull pv2 = dup2(pv);
                        ac2[i][0] = ffma2(pv2, v0.x, ac2[i][0]);
                        ac2[i][1] = ffma2(pv2, v0.y, ac2[i][1]);
                        ac2[i][2] = ffma2(pv2, v1.x, ac2[i][2]);
                        ac2[i][3] = ffma2(pv2, v1.y, ac2[i][3]);
                    }
                }
            }
        }
        __syncthreads();               // all threads done reading Vs

        // ---- issue V(tile+1) into Vs (overlaps next QK) ----
        if (more) {
            const float4* vs = vbase + (size_t)(tile + 1) * 2048;
            #pragma unroll
            for (int i = 0; i < 8; i++) {
                int idx = t + i * 256; int r = idx >> 5, c = idx & 31;
                uint32_t off = (uint32_t)(r * 32 + (c ^ ((r >> 2) & 7))) * 16u;
                cp16(vd + off, vs + idx);
            }
            cp_commit();
        }
    }

    // ---- write partials (unnormalized) ----
    #pragma unroll
    for (int i = 0; i < 4; i++) {
        size_t prow = ((size_t)z * NB + b) * TQ + qb * 64 + 4 * tq + i;
        float2 a0 = u2f(ac2[i][0]), a1 = u2f(ac2[i][1]);
        float2 a2 = u2f(ac2[i][2]), a3 = u2f(ac2[i][3]);
        *(float4*)(g_ao + prow * HD + 4 * tk)      = make_float4(a0.x, a0.y, a1.x, a1.y);
        *(float4*)(g_ao + prow * HD + 64 + 4 * tk) = make_float4(a2.x, a2.y, a3.x, a3.y);
        if (tk == 0) { g_am[prow] = m[i]; g_al[prow] = l[i]; }
    }
}

// =========================================================================
// 3b) attention partial merge (unchanged)
// =========================================================================
__global__ __launch_bounds__(256) void attn_merge_kernel(
    const float* __restrict__ gate, float* __restrict__ out)
{
    const int idx = blockIdx.x * 256 + threadIdx.x;
    const int row = idx >> 5;
    const float m0 = g_am[row], m1 = g_am[NB * TQ + row];
    const float l0 = g_al[row], l1 = g_al[NB * TQ + row];
    const float M  = fmaxf(m0, m1);
    const float w0 = __expf(m0 - M), w1 = __expf(m1 - M);
    const float inv = gate[0] / (w0 * l0 + w1 * l1);
    float4 a0 = ((const float4*)g_ao)[idx];
    float4 a1 = ((const float4*)g_ao)[(size_t)NB * TQ * 32 + idx];
    float4 o;
    o.x = (w0 * a0.x + w1 * a1.x) * inv;
    o.y = (w0 * a0.y + w1 * a1.y) * inv;
    o.z = (w0 * a0.z + w1 * a1.z) * inv;
    o.w = (w0 * a0.w + w1 * a1.w) * inv;
    ((float4*)out)[idx] = o;
}

// =========================================================================
// 4) kNN memory attention v5 (R14 passing version, byte-identical)
// =========================================================================
#define MEM_SMEM (81920)

__global__ __launch_bounds__(128, 2) void mem_kernel(
    const float* __restrict__ mem_vals,
    const float* __restrict__ gate, float* __restrict__ out)
{
    extern __shared__ float msm[];
    float4* Qs  = (float4*)msm;
    float4* Ks0 = (float4*)(msm + 4096);
    float4* Ks1 = (float4*)(msm + 12288);
    float*  lv_s = msm;
    int*    li_s = (int*)(msm + 4096);

    const int t    = threadIdx.x;
    const int b    = blockIdx.y;
    const int q0   = blockIdx.x * 32;
    const int tq2  = t >> 4;
    const int g    = t & 15;
    const int o    = g >> 2;
    const int sk   = g & 7;
    const int lane = t & 31;

    const float4* qsrc = (const float4*)(g_q + ((size_t)(b * TQ + q0)) * HD);
    #pragma unroll
    for (int i = 0; i < 8; i++) {
        int idx = t + i * 128; int r = idx >> 5, c = idx & 31;
        Qs[r * 32 + (c ^ (r & 7))] = qsrc[idx];
    }

    float lv[32]; int li[32];
    #pragma unroll
    for (int i = 0; i < 32; i++) { lv[i] = -1e30f; li[i] = 0; }
    float Tsh = -1e30f;

    const float4* kb = (const float4*)g_ki + (size_t)b * 8192 * 64;

    {
        uint32_t kd = (uint32_t)__cvta_generic_to_shared(Ks0);
        #pragma unroll
        for (int i = 0; i < 16; i++) {
            int idx = t + i * 128; int row = idx >> 6, col = idx & 63;
            uint32_t off = (uint32_t)(row * 64 + (col ^ ((row >> 1) & 7))) * 16u;
            cp16(kd + off, kb + idx);
        }
        cp_commit();
    }

    for (int tile = 0; tile < NM / 64; tile++) {
        cp_wait0();
        __syncthreads();
        const float4* Ks = (tile & 1) ? Ks1 : Ks0;

        if (tile + 1 < NM / 64) {
            float4* Kn = (tile & 1) ? Ks0 : Ks1;
            uint32_t kd = (uint32_t)__cvta_generic_to_shared(Kn);
            const float4* ks = kb + (size_t)(tile + 1) * 2048;
            #pragma unroll
            for (int i = 0; i < 16; i++) {
                int idx = t + i * 128; int row = idx >> 6, col = idx & 63;
                uint32_t off = (uint32_t)(row * 64 + (col ^ ((row >> 1) & 7))) * 16u;
                cp16(kd + off, ks + idx);
            }
            cp_commit();
        }

        ull acc[4][2];
        #pragma unroll
        for (int i = 0; i < 4; i++) { acc[i][0] = 0ULL; acc[i][1] = 0ULL; }

        #pragma unroll 4
        for (int c = 0; c < 32; c++) {
            ull ax[4], ay[4], az[4], aw[4];
            #pragma unroll
            for (int i = 0; i < 4; i++) {
                int q = 4 * tq2 + i;
                float4 a = Qs[q * 32 + (c ^ (q & 7))];
                ax[i] = dup2(a.x); ay[i] = dup2(a.y);
                az[i] = dup2(a.z); aw[i] = dup2(a.w);
            }
            #pragma unroll
            for (int jj = 0; jj < 2; jj++) {
                int base = (2 * g + jj) * 64;
                ulonglong2 k01 = *(const ulonglong2*)&Ks[base + ((2 * c)     ^ sk)];
                ulonglong2 k23 = *(const ulonglong2*)&Ks[base + ((2 * c + 1) ^ sk)];
                #pragma unroll
                for (int i = 0; i < 4; i++) {
                    acc[i][jj] = ffma2(ax[i], k01.x, acc[i][jj]);
                    acc[i][jj] = ffma2(ay[i], k01.y, acc[i][jj]);
                    acc[i][jj] = ffma2(az[i], k23.x, acc[i][jj]);
                    acc[i][jj] = ffma2(aw[i], k23.y, acc[i][jj]);
                }
            }
        }

        float s[4][4];
        #pragma unroll
        for (int i = 0; i < 4; i++) {
            float2 p0 = u2f(acc[i][0]);
            float2 p1 = u2f(acc[i][1]);
            s[i][0] = p0.x; s[i][1] = p0.y;
            s[i][2] = p1.x; s[i][3] = p1.y;
        }

        #pragma unroll
        for (int r = 0; r < 4; r++) {
            const int qs  = o ^ r;
            const int src = g ^ (r << 2);
            const int kb0 = tile * 64 + 4 * src;
            #pragma unroll
            for (int j = 0; j < 4; j++) {
                float cv = (r == 0) ? s[o][j]
                         : __shfl_xor_sync(0xffffffffu, s[qs][j], r << 2);
                if (cv > fmaxf(Tsh, lv[31])) {
                    int kidx = kb0 + j;
                    bool pp = true;
                    #pragma unroll
                    for (int p = 31; p >= 1; p--) {
                        bool pr = lv[p - 1] < cv;
                        float nv = pr ? lv[p - 1] : (pp ? cv : lv[p]);
                        int   ni = pr ? li[p - 1] : (pp ? kidx : li[p]);
                        lv[p] = nv; li[p] = ni;
                        pp = pr;
                    }
                    if (pp) { lv[0] = cv; li[0] = kidx; }
                }
            }
        }
        {
            float tm = lv[31];
            tm = fmaxf(tm, __shfl_xor_sync(0xffffffffu, tm, 1));
            tm = fmaxf(tm, __shfl_xor_sync(0xffffffffu, tm, 2));
            Tsh = tm;
        }
        __syncthreads();
    }

    #pragma unroll
    for (int p = 0; p < 32; p++) {
        lv_s[p * 128 + t] = lv[p];
        li_s[p * 128 + t] = li[p];
    }
    __syncthreads();

    const float* vb = mem_vals + (size_t)b * NM * HD;
    const float scg = 1.0f - gate[0];

    for (int pass = 0; pass < 4; pass++) {
        const bool mine = (o == pass);
        float accv[8];
        #pragma unroll
        for (int u = 0; u < 8; u++) accv[u] = 0.f;
        float sumw = 0.f, vmax = 0.f;
        int ptr = 0;

        for (int it = 0; it < 32; it++) {
            float bv = (mine && ptr < 32) ? lv_s[ptr * 128 + t] : -1e30f;
            int   wl = lane;
            #pragma unroll
            for (int off = 1; off < 16; off <<= 1) {
                float ov = __shfl_xor_sync(0xffffffffu, bv, off);
                int   ol = __shfl_xor_sync(0xffffffffu, wl, off);
                if (ov > bv) { bv = ov; wl = ol; }
            }
            int myi  = li_s[(ptr < 32 ? ptr : 31) * 128 + t];
            int widx = __shfl_sync(0xffffffffu, myi, wl);
            if (lane == wl) ptr++;
            if (it == 0) vmax = bv;
            float w = __expf((bv - vmax) * 0.03125f);
            sumw += w;
            const float4* vrow = (const float4*)(vb + (size_t)widx * HD) + g * 2;
            #pragma unroll
            for (int u = 0; u < 2; u++) {
                float4 vv = vrow[u];
                accv[4 * u + 0] = fmaf(w, vv.x, accv[4 * u + 0]);
                accv[4 * u + 1] = fmaf(w, vv.y, accv[4 * u + 1]);
                accv[4 * u + 2] = fmaf(w, vv.z, accv[4 * u + 2]);
                accv[4 * u + 3] = fmaf(w, vv.w, accv[4 * u + 3]);
            }
        }

        const float sc = scg / sumw;
        const int   qq = q0 + 4 * tq2 + pass;
        float* orow = out + ((size_t)(b * TQ + qq)) * HD + g * 8;
        #pragma unroll
        for (int u = 0; u < 2; u++) {
            float4 ov = ((float4*)orow)[u];
            ov.x += sc * accv[4 * u + 0];
            ov.y += sc * accv[4 * u + 1];
            ov.z += sc * accv[4 * u + 2];
            ov.w += sc * accv[4 * u + 3];
            ((float4*)orow)[u] = ov;
        }
    }
}

// =========================================================================
extern "C" void kernel_launch(void* const* d_in, const int* in_sizes, int n_in,
                              void* d_out, int out_size) {
    const float* x        = (const float*)d_in[0];
    const float* ki       = (const float*)d_in[1];
    const float* vi       = (const float*)d_in[2];
    const float* mem_keys = (const float*)d_in[3];
    const float* mem_vals = (const float*)d_in[4];
    const float* Wq       = (const float*)d_in[5];
    const float* bq       = (const float*)d_in[6];
    const float* Wk       = (const float*)d_in[7];
    const float* bk       = (const float*)d_in[8];
    const float* Wv       = (const float*)d_in[9];
    const float* bv       = (const float*)d_in[10];
    const float* gate     = (const float*)d_in[11];
    const int*   idxp     = (const int*)d_in[12];
    float* out = (float*)d_out;

    cudaFuncSetAttribute(attn_kernel, cudaFuncAttributeMaxDynamicSharedMemorySize,
                         ATTN_SMEM);
    cudaFuncSetAttribute(mem_kernel, cudaFuncAttributeMaxDynamicSharedMemorySize,
                         MEM_SMEM);

    interleave_kernel<<<8192, 256>>>(mem_keys);
    copy_prefix_kernel<<<1024, 256>>>(ki, vi, idxp);
    proj_kernel<<<dim3(128, 3), 256>>>(x, Wq, Wk, Wv, bq, bk, bv);
    attn_kernel<<<dim3(32, 4, 2), 256, ATTN_SMEM>>>();
    attn_merge_kernel<<<1024, 256>>>(gate, out);
    mem_kernel<<<dim3(64, 4), 128, MEM_SMEM>>>(mem_vals, gate, out);
}